// round 13
// baseline (speedup 1.0000x reference)
#include <cuda_runtime.h>
#include <cuda_fp16.h>
#include <math.h>
#include <stdint.h>

#define NSENT 4096
#define NWORD 65536
#define NSEC  512
#define NHEAD 8
#define CDIM  640
#define HC    5120
#define EW    65536
#define ES    32768
#define ESEC  4096
#define NEG_SLOPE 0.2f

// ---------------- scratch (__device__ globals, no allocation) ----------------
__device__ float g_Uw[NSENT*HC];
__device__ float g_Us[NSENT*HC];
__device__ float g_USec[NSENT*HC];
__device__ float g_U1[NSENT*HC];
__device__ float g_Hh[NSENT*CDIM];
__device__ float g_U2[NSENT*HC];
// fp16 operand copies (GEMM A inputs)
__device__ __half g_Uwh[NSENT*HC];
__device__ __half g_Ush[NSENT*HC];
__device__ __half g_USech[NSENT*HC];
__device__ __half g_U1h[NSENT*HC];
__device__ __half g_U2h[NSENT*HC];
__device__ __half g_Hhh[NSENT*CDIM];
__device__ __half g_Gwh[NSENT*NHEAD*320];
__device__ __half g_Gsh[NSENT*NHEAD*640];
__device__ __half g_GSh[NSENT*NHEAD*512];
// fp16 K-major transposed weights (GEMM B inputs, [N][K])
__device__ __half g_Wf1Th[(long)HC*2*HC];
__device__ __half g_Wf2Th[(long)HC*2*HC];
__device__ __half g_W1Th[CDIM*HC];
__device__ __half g_W2Th[CDIM*CDIM];
__device__ __half g_WwTh[NHEAD*CDIM*320];
__device__ __half g_WsTh[NHEAD*CDIM*640];
__device__ __half g_WSTh[NHEAD*CDIM*512];
// graph scratch
__device__ float g_Pws[300*8], g_Pwd[640*8], g_Pss[640*8], g_Psd[640*8], g_PSs[512*8], g_PSd[640*8];
__device__ float g_alws[NWORD*8];
__device__ float g_alwd[NSENT*8], g_alss[NSENT*8], g_alsd[NSENT*8], g_alSd[NSENT*8];
__device__ float g_alSs[NSEC*8];
__device__ float g_aw[EW*8], g_as[ES*8], g_aS[ESEC*8];
__device__ int   g_mw[NSENT*8], g_ms[NSENT*8], g_mS[NSENT*8];
__device__ float g_dw[NSENT*8], g_ds[NSENT*8], g_dS[NSENT*8];
__device__ int   g_cw[NSENT], g_cs[NSENT], g_cS[NSENT];
__device__ int   g_ow[NSENT+1], g_os[NSENT+1], g_oS[NSENT+1];
__device__ int   g_uw[NSENT], g_us[NSENT], g_uS[NSENT];
__device__ int   g_ew[EW], g_es[ES], g_eS[ESEC];

// ---------------- helpers ----------------
__device__ __forceinline__ int f2oi(float f){ int i=__float_as_int(f); return i>=0? i : (i ^ 0x7fffffff); }
__device__ __forceinline__ float oi2f(int i){ return __int_as_float(i>=0? i : (i ^ 0x7fffffff)); }

// ---------------- init ----------------
__global__ void k_init_all(int* m0, float* d0, int* c0,
                           int* m1, float* d1, int* c1,
                           int* m2, float* d2, int* c2){
    int i = blockIdx.x*blockDim.x + threadIdx.x;
    if (i < NSENT*8){
        m0[i] = (int)0x807FFFFF; d0[i] = 0.f;
        m1[i] = (int)0x807FFFFF; d1[i] = 0.f;
        m2[i] = (int)0x807FFFFF; d2[i] = 0.f;
    }
    if (i < NSENT){ c0[i] = 0; c1[i] = 0; c2[i] = 0; }
}

// ---------------- transpose + fp16 convert: BT[z][n][k] = (half)W[k][z*colstride + n] ----------------
__global__ void k_Tc(const float* __restrict__ W, __half* __restrict__ BT,
                     int Kin, int Kpad, int Nsub, int ldw, int colstride){
    __shared__ float t[32][33];
    int nb = blockIdx.x*32, kb = blockIdx.y*32;
    int x = threadIdx.x, y = threadIdx.y;
    long coff = (long)blockIdx.z*colstride;
    #pragma unroll
    for (int j = 0; j < 32; j += 8){
        int k = kb + y + j, n = nb + x;
        t[y+j][x] = (k < Kin && n < Nsub) ? W[(long)k*ldw + coff + n] : 0.f;
    }
    __syncthreads();
    __half* out = BT + (long)blockIdx.z*Nsub*Kpad;
    #pragma unroll
    for (int j = 0; j < 32; j += 8){
        int n = nb + y + j, k = kb + x;
        if (n < Nsub && k < Kpad) out[(long)n*Kpad + k] = __float2half_rn(t[x][y+j]);
    }
}

// ---------------- P[d,h] ----------------
__global__ void k_P(const float* __restrict__ W, const float* __restrict__ a,
                    float* __restrict__ P, int D){
    int gw   = (blockIdx.x*blockDim.x + threadIdx.x) >> 5;
    int lane = threadIdx.x & 31;
    if (gw >= D*8) return;
    int d = gw >> 3, h = gw & 7;
    const float* wr = W + (long)d*HC + h*CDIM;
    const float* ar = a + h*CDIM;
    float acc = 0.f;
    for (int c = lane; c < CDIM; c += 32) acc = fmaf(__ldg(&wr[c]), __ldg(&ar[c]), acc);
    #pragma unroll
    for (int o = 16; o; o >>= 1) acc += __shfl_xor_sync(0xffffffffu, acc, o);
    if (!lane) P[gw] = acc;
}

// ---------------- AL[n,h] ----------------
__global__ void k_xp(const float* __restrict__ X, const float* __restrict__ P,
                     float* __restrict__ AL, int N, int D){
    int row  = (blockIdx.x*blockDim.x + threadIdx.x) >> 5;
    int lane = threadIdx.x & 31;
    if (row >= N) return;
    const float* x = X + (long)row*D;
    float acc[8] = {0,0,0,0,0,0,0,0};
    for (int dd = lane; dd < D; dd += 32){
        float xv = __ldg(&x[dd]);
        const float* p = P + dd*8;
        #pragma unroll
        for (int h = 0; h < 8; h++) acc[h] = fmaf(xv, __ldg(&p[h]), acc[h]);
    }
    #pragma unroll
    for (int h = 0; h < 8; h++){
        #pragma unroll
        for (int o = 16; o; o >>= 1) acc[h] += __shfl_xor_sync(0xffffffffu, acc[h], o);
    }
    if (lane == 0){
        #pragma unroll
        for (int h = 0; h < 8; h++) AL[(long)row*8 + h] = acc[h];
    }
}

// ---------------- edge softmax ----------------
__global__ void k_logits(const int* __restrict__ src, const int* __restrict__ dst,
                         const float* __restrict__ als, const float* __restrict__ ald,
                         float* __restrict__ lg, int* __restrict__ segmax, int E){
    int e = blockIdx.x*blockDim.x + threadIdx.x;
    if (e >= E) return;
    int s = src[e], d = dst[e];
    #pragma unroll
    for (int h = 0; h < 8; h++){
        float v = __ldg(&als[s*8+h]) + __ldg(&ald[d*8+h]);
        v = v > 0.f ? v : NEG_SLOPE*v;
        lg[e*8+h] = v;
        atomicMax(&segmax[d*8+h], f2oi(v));
    }
}
__global__ void k_exp(const int* __restrict__ dst, float* __restrict__ lg,
                      const int* __restrict__ segmax, float* __restrict__ den, int E){
    int e = blockIdx.x*blockDim.x + threadIdx.x;
    if (e >= E) return;
    int d = dst[e];
    #pragma unroll
    for (int h = 0; h < 8; h++){
        float m  = oi2f(__ldg(&segmax[d*8+h]));
        float ex = expf(lg[e*8+h] - m);
        lg[e*8+h] = ex;
        atomicAdd(&den[d*8+h], ex);
    }
}
__global__ void k_alpha(const int* __restrict__ dst, float* __restrict__ lg,
                        const float* __restrict__ den, int E){
    int e = blockIdx.x*blockDim.x + threadIdx.x;
    if (e >= E) return;
    int d = dst[e];
    #pragma unroll
    for (int h = 0; h < 8; h++)
        lg[e*8+h] = lg[e*8+h] / (__ldg(&den[d*8+h]) + 1e-16f);
}

// ---------------- CSR build ----------------
__global__ void k_count(const int* __restrict__ dst, int* __restrict__ cnt, int E){
    int e = blockIdx.x*blockDim.x + threadIdx.x;
    if (e < E) atomicAdd(&cnt[dst[e]], 1);
}
__global__ void k_scan(const int* __restrict__ cnt, int* __restrict__ offs,
                       int* __restrict__ cur){
    __shared__ int sh[1024];
    int tid = threadIdx.x;
    int base = tid*4;
    int v0 = cnt[base], v1 = cnt[base+1], v2 = cnt[base+2], v3 = cnt[base+3];
    int sum = v0+v1+v2+v3;
    sh[tid] = sum; __syncthreads();
    for (int off = 1; off < 1024; off <<= 1){
        int t = (tid >= off) ? sh[tid-off] : 0;
        __syncthreads();
        sh[tid] += t;
        __syncthreads();
    }
    int run = sh[tid] - sum;
    offs[base] = run;   cur[base]   = run; run += v0;
    offs[base+1] = run; cur[base+1] = run; run += v1;
    offs[base+2] = run; cur[base+2] = run; run += v2;
    offs[base+3] = run; cur[base+3] = run; run += v3;
    if (tid == 1023) offs[NSENT] = run;
}
__global__ void k_scatter(const int* __restrict__ dst, int* __restrict__ cur,
                          int* __restrict__ eidx, int E){
    int e = blockIdx.x*blockDim.x + threadIdx.x;
    if (e < E) eidx[atomicAdd(&cur[dst[e]], 1)] = e;
}

// ---------------- per-dst aggregation -> fp16 (padded K) ----------------
template<int D, int DPAD, int COLS>
__global__ void k_agg(const float* __restrict__ X, const int* __restrict__ src,
                      const int* __restrict__ eidx, const int* __restrict__ offs,
                      const float* __restrict__ alpha, __half* __restrict__ G){
    int d = blockIdx.x, tid = threadIdx.x;
    float acc[COLS][8];
    #pragma unroll
    for (int ci = 0; ci < COLS; ci++)
        #pragma unroll
        for (int h = 0; h < 8; h++) acc[ci][h] = 0.f;
    int beg = offs[d], end = offs[d+1];
    for (int i = beg; i < end; i++){
        int e = eidx[i];
        int s = src[e];
        float a[8];
        #pragma unroll
        for (int h = 0; h < 8; h++) a[h] = __ldg(&alpha[e*8+h]);
        #pragma unroll
        for (int ci = 0; ci < COLS; ci++){
            int c = tid + ci*256;
            if (c < D){
                float x = __ldg(&X[(long)s*D + c]);
                #pragma unroll
                for (int h = 0; h < 8; h++) acc[ci][h] = fmaf(a[h], x, acc[ci][h]);
            }
        }
    }
    #pragma unroll
    for (int ci = 0; ci < COLS; ci++){
        int c = tid + ci*256;
        if (c < DPAD){
            #pragma unroll
            for (int h = 0; h < 8; h++){
                float v = (c < D) ? acc[ci][h] : 0.f;
                G[((long)d*8 + h)*DPAD + c] = __float2half_rn(v);
            }
        }
    }
}

// ---------------- FP16 tensor-core GEMM 128x128x32, half operands, double-buffered ----------------
// A [M][Ktot] half K-major (split A/A2 at ksplit, both mult of 32); BT [N][Ktot] half K-major.
#define STR 136
enum { EPI_BIAS_ELU = 0, EPI_BIAS_RELU, EPI_FUSION, EPI_RESID };

__device__ __forceinline__ void mma_f16(float* d, const uint32_t* a, const uint32_t* b){
    asm volatile(
        "mma.sync.aligned.m16n8k16.row.col.f32.f16.f16.f32 "
        "{%0,%1,%2,%3}, {%4,%5,%6,%7}, {%8,%9}, {%0,%1,%2,%3};"
        : "+f"(d[0]), "+f"(d[1]), "+f"(d[2]), "+f"(d[3])
        : "r"(a[0]), "r"(a[1]), "r"(a[2]), "r"(a[3]), "r"(b[0]), "r"(b[1]));
}

template<int EPI>
__global__ __launch_bounds__(256,2)
void gemm_h(const __half* __restrict__ A, const __half* __restrict__ A2, int ksplit,
            const __half* __restrict__ BT, float* __restrict__ C, __half* __restrict__ Ch,
            const float* __restrict__ bias,
            const float* __restrict__ E0, const float* __restrict__ E1,
            int M, int N, int Ktot, int lda, int ldbt, int ldc,
            long sA, long sBT, long sC, int sBias){
    int z = blockIdx.z;
    A  += (long)z*sA;  A2 += (long)z*sA;  BT += (long)z*sBT;  C += (long)z*sC;
    if (Ch) Ch += (long)z*sC;
    const float* bp = bias + (long)z*sBias;

    __shared__ uint32_t As2[2][16*STR];
    __shared__ uint32_t Bs2[2][16*STR];
    int tid  = threadIdx.x;
    int wid  = tid >> 5, lane = tid & 31;
    int g    = lane >> 2, tig = lane & 3;
    int wm   = wid & 3, wn = wid >> 2;          // warp tile: 32(M) x 64(N)
    int m0   = wm*32, n0 = wn*64;
    int bRow = blockIdx.y*128, bCol = blockIdx.x*128;
    int r    = tid & 127, kh = tid >> 7;        // staging: row r, k-half kh (16 k each)

    float acc[2][8][4];
    #pragma unroll
    for (int mi = 0; mi < 2; mi++)
        #pragma unroll
        for (int j = 0; j < 8; j++)
            #pragma unroll
            for (int c = 0; c < 4; c++) acc[mi][j][c] = 0.f;

    uint4 pa0, pa1, pb0, pb1;
    auto ldg = [&](int t){
        int k = t*32 + kh*16;
        const __half* p = (k < ksplit) ? (A  + (long)(bRow + r)*lda + k)
                                       : (A2 + (long)(bRow + r)*lda + (k - ksplit));
        pa0 = *reinterpret_cast<const uint4*>(p);
        pa1 = *reinterpret_cast<const uint4*>(p + 8);
        const __half* q = BT + (long)(bCol + r)*ldbt + k;
        pb0 = *reinterpret_cast<const uint4*>(q);
        pb1 = *reinterpret_cast<const uint4*>(q + 8);
    };
    auto sts = [&](int b){
        uint32_t* a  = &As2[b][(kh*8)*STR + r];
        uint32_t* bq = &Bs2[b][(kh*8)*STR + r];
        const uint32_t* s0 = reinterpret_cast<const uint32_t*>(&pa0);
        const uint32_t* s1 = reinterpret_cast<const uint32_t*>(&pa1);
        const uint32_t* t0 = reinterpret_cast<const uint32_t*>(&pb0);
        const uint32_t* t1 = reinterpret_cast<const uint32_t*>(&pb1);
        #pragma unroll
        for (int i = 0; i < 4; i++){ a[i*STR]      = s0[i]; a[(i+4)*STR]  = s1[i]; }
        #pragma unroll
        for (int i = 0; i < 4; i++){ bq[i*STR]     = t0[i]; bq[(i+4)*STR] = t1[i]; }
    };

    int T = Ktot >> 5;
    ldg(0); sts(0);
    __syncthreads();
    for (int t = 0; t < T; t++){
        int b = t & 1;
        if (t + 1 < T) ldg(t + 1);
        #pragma unroll
        for (int ks = 0; ks < 2; ks++){
            int kb = ks*8;
            uint32_t af[2][4];
            #pragma unroll
            for (int mi = 0; mi < 2; mi++){
                int mb = m0 + mi*16;
                af[mi][0] = As2[b][(kb+tig  )*STR + mb + g    ];
                af[mi][1] = As2[b][(kb+tig  )*STR + mb + g + 8];
                af[mi][2] = As2[b][(kb+tig+4)*STR + mb + g    ];
                af[mi][3] = As2[b][(kb+tig+4)*STR + mb + g + 8];
            }
            #pragma unroll
            for (int j = 0; j < 8; j++){
                int n = n0 + j*8 + g;
                uint32_t bf[2];
                bf[0] = Bs2[b][(kb+tig  )*STR + n];
                bf[1] = Bs2[b][(kb+tig+4)*STR + n];
                mma_f16(acc[0][j], af[0], bf);
                mma_f16(acc[1][j], af[1], bf);
            }
        }
        if (t + 1 < T) sts(b ^ 1);
        __syncthreads();
    }

    // epilogue: thread owns rows (m0+mi*16+g, +8), cols (n0+j*8+tig*2, +1)
    #pragma unroll
    for (int mi = 0; mi < 2; mi++){
        #pragma unroll
        for (int half = 0; half < 2; half++){
            int row = bRow + m0 + mi*16 + g + half*8;
            #pragma unroll
            for (int j = 0; j < 8; j++){
                int col = bCol + n0 + j*8 + tig*2;
                long idx = (long)row*ldc + col;
                float v0 = acc[mi][j][half*2+0] + bp[col];
                float v1 = acc[mi][j][half*2+1] + bp[col+1];
                float r0, r1;
                if (EPI == EPI_BIAS_ELU){
                    r0 = v0 > 0.f ? v0 : (expf(v0) - 1.f);
                    r1 = v1 > 0.f ? v1 : (expf(v1) - 1.f);
                } else if (EPI == EPI_BIAS_RELU){
                    r0 = fmaxf(v0, 0.f);
                    r1 = fmaxf(v1, 0.f);
                } else if (EPI == EPI_FUSION){
                    float z0 = 1.f/(1.f + expf(-v0));
                    float z1 = 1.f/(1.f + expf(-v1));
                    r0 = z0*E0[idx]   + (1.f - z0)*E1[idx];
                    r1 = z1*E0[idx+1] + (1.f - z1)*E1[idx+1];
                } else { // EPI_RESID
                    r0 = E0[idx]   + v0;
                    r1 = E0[idx+1] + v1;
                }
                *reinterpret_cast<float2*>(&C[idx]) = make_float2(r0, r1);
                if (Ch){
                    __half2 h2 = __floats2half2_rn(r0, r1);
                    *reinterpret_cast<__half2*>(&Ch[idx]) = h2;
                }
            }
        }
    }
}

// ---------------- host ----------------
#define SYMF(name, sym) float* name; cudaGetSymbolAddress((void**)&name, sym)
#define SYMH(name, sym) __half* name; cudaGetSymbolAddress((void**)&name, sym)
#define SYMI(name, sym) int*   name; cudaGetSymbolAddress((void**)&name, sym)

extern "C" void kernel_launch(void* const* d_in, const int* in_sizes, int n_in,
                              void* d_out, int out_size){
    const float* Hs    = (const float*)d_in[0];
    const float* Hw    = (const float*)d_in[1];
    const float* HSc   = (const float*)d_in[2];
    const int*   w2s   = (const int*)d_in[3];
    const int*   s2s   = (const int*)d_in[4];
    const int*   S2s   = (const int*)d_in[5];
    const float* Ww_src= (const float*)d_in[6];
    const float* Ww_dst= (const float*)d_in[7];
    const float* aw_src= (const float*)d_in[8];
    const float* aw_dst= (const float*)d_in[9];
    const float* bw    = (const float*)d_in[10];
    const float* Ws    = (const float*)d_in[11];
    const float* as_src= (const float*)d_in[12];
    const float* as_dst= (const float*)d_in[13];
    const float* bs    = (const float*)d_in[14];
    const float* WS_src= (const float*)d_in[15];
    const float* WS_dst= (const float*)d_in[16];
    const float* aS_src= (const float*)d_in[17];
    const float* aS_dst= (const float*)d_in[18];
    const float* bS    = (const float*)d_in[19];
    const float* Wf1   = (const float*)d_in[20];
    const float* bf1   = (const float*)d_in[21];
    const float* Wf2   = (const float*)d_in[22];
    const float* bf2   = (const float*)d_in[23];
    const float* W1    = (const float*)d_in[24];
    const float* b1    = (const float*)d_in[25];
    const float* W2    = (const float*)d_in[26];
    const float* b2    = (const float*)d_in[27];
    float* out = (float*)d_out;

    SYMF(Uw, g_Uw); SYMF(Us, g_Us); SYMF(USec, g_USec); SYMF(U1, g_U1); SYMF(U2, g_U2); SYMF(Hh, g_Hh);
    SYMH(Uwh, g_Uwh); SYMH(Ush, g_Ush); SYMH(USech, g_USech); SYMH(U1h, g_U1h); SYMH(U2h, g_U2h); SYMH(Hhh, g_Hhh);
    SYMH(Gwh, g_Gwh); SYMH(Gsh, g_Gsh); SYMH(GSh, g_GSh);
    SYMH(Wf1Th, g_Wf1Th); SYMH(Wf2Th, g_Wf2Th); SYMH(W1Th, g_W1Th); SYMH(W2Th, g_W2Th);
    SYMH(WwTh, g_WwTh); SYMH(WsTh, g_WsTh); SYMH(WSTh, g_WSTh);
    SYMF(Pws, g_Pws); SYMF(Pwd, g_Pwd); SYMF(Pss, g_Pss); SYMF(Psd, g_Psd);
    SYMF(PSs, g_PSs); SYMF(PSd, g_PSd);
    SYMF(alws, g_alws); SYMF(alwd, g_alwd); SYMF(alss, g_alss); SYMF(alsd, g_alsd);
    SYMF(alSs, g_alSs); SYMF(alSd, g_alSd);
    SYMF(aw, g_aw); SYMF(as, g_as); SYMF(aS, g_aS);
    SYMI(mw, g_mw); SYMI(ms, g_ms); SYMI(mS, g_mS);
    SYMF(dw, g_dw); SYMF(ds, g_ds); SYMF(dS, g_dS);
    SYMI(cw, g_cw); SYMI(cs, g_cs); SYMI(cS, g_cS);
    SYMI(ow, g_ow); SYMI(os_, g_os); SYMI(oS, g_oS);
    SYMI(uw, g_uw); SYMI(us, g_us); SYMI(uS, g_uS);
    SYMI(ew, g_ew); SYMI(es, g_es); SYMI(eS, g_eS);

    const int* src_w = w2s;            const int* dst_w = w2s + EW;
    const int* src_s = s2s;            const int* dst_s = s2s + ES;
    const int* src_S = S2s;            const int* dst_S = S2s + ESEC;

    // init
    k_init_all<<<(NSENT*8+255)/256, 256>>>(mw, dw, cw, ms, ds, cs, mS, dS, cS);

    // weight transpose + fp16 convert  (BT[z][n][k] layouts)
    dim3 tb(32, 8);
    k_Tc<<<dim3(20, 10, 8),   tb>>>(Ww_src, WwTh, 300,  320,  CDIM, HC,   CDIM);
    k_Tc<<<dim3(20, 20, 8),   tb>>>(Ws,     WsTh, 640,  640,  CDIM, HC,   CDIM);
    k_Tc<<<dim3(20, 16, 8),   tb>>>(WS_src, WSTh, 512,  512,  CDIM, HC,   CDIM);
    k_Tc<<<dim3(160, 320, 1), tb>>>(Wf1,    Wf1Th, 2*HC, 2*HC, HC,  HC,   0);
    k_Tc<<<dim3(160, 320, 1), tb>>>(Wf2,    Wf2Th, 2*HC, 2*HC, HC,  HC,   0);
    k_Tc<<<dim3(20, 160, 1),  tb>>>(W1,     W1Th,  HC,   HC,   CDIM, CDIM, 0);
    k_Tc<<<dim3(20, 20, 1),   tb>>>(W2,     W2Th,  CDIM, CDIM, CDIM, CDIM, 0);

    // per-head attention projection vectors
    k_P<<<300, 256>>>(Ww_src, aw_src, Pws, 300);
    k_P<<<640, 256>>>(Ww_dst, aw_dst, Pwd, 640);
    k_P<<<640, 256>>>(Ws,     as_src, Pss, 640);
    k_P<<<640, 256>>>(Ws,     as_dst, Psd, 640);
    k_P<<<512, 256>>>(WS_src, aS_src, PSs, 512);
    k_P<<<640, 256>>>(WS_dst, aS_dst, PSd, 640);

    // attention logits per node
    k_xp<<<NWORD/8, 256>>>(Hw,  Pws, alws, NWORD, 300);
    k_xp<<<NSENT/8, 256>>>(Hs,  Pwd, alwd, NSENT, 640);
    k_xp<<<NSENT/8, 256>>>(Hs,  Pss, alss, NSENT, 640);
    k_xp<<<NSENT/8, 256>>>(Hs,  Psd, alsd, NSENT, 640);
    k_xp<<<NSEC/8,  256>>>(HSc, PSs, alSs, NSEC,  512);
    k_xp<<<NSENT/8, 256>>>(Hs,  PSd, alSd, NSENT, 640);

    // CSR build
    k_count<<<EW/256, 256>>>(dst_w, cw, EW);
    k_count<<<ES/256, 256>>>(dst_s, cs, ES);
    k_count<<<ESEC/256, 256>>>(dst_S, cS, ESEC);
    k_scan<<<1, 1024>>>(cw, ow, uw);
    k_scan<<<1, 1024>>>(cs, os_, us);
    k_scan<<<1, 1024>>>(cS, oS, uS);
    k_scatter<<<EW/256, 256>>>(dst_w, uw, ew, EW);
    k_scatter<<<ES/256, 256>>>(dst_s, us, es, ES);
    k_scatter<<<ESEC/256, 256>>>(dst_S, uS, eS, ESEC);

    // edge softmax
    k_logits<<<EW/256, 256>>>(src_w, dst_w, alws, alwd, aw, mw, EW);
    k_logits<<<ES/256, 256>>>(src_s, dst_s, alss, alsd, as, ms, ES);
    k_logits<<<ESEC/256, 256>>>(src_S, dst_S, alSs, alSd, aS, mS, ESEC);
    k_exp<<<EW/256, 256>>>(dst_w, aw, mw, dw, EW);
    k_exp<<<ES/256, 256>>>(dst_s, as, ms, ds, ES);
    k_exp<<<ESEC/256, 256>>>(dst_S, aS, mS, dS, ESEC);
    k_alpha<<<EW/256, 256>>>(dst_w, aw, dw, EW);
    k_alpha<<<ES/256, 256>>>(dst_s, as, ds, ES);
    k_alpha<<<ESEC/256, 256>>>(dst_S, aS, dS, ESEC);

    // aggregate raw features per (dst, head) -> fp16 (K padded)
    k_agg<300,320,2><<<NSENT, 256>>>(Hw,  src_w, ew, ow,  aw, Gwh);
    k_agg<640,640,3><<<NSENT, 256>>>(Hs,  src_s, es, os_, as, Gsh);
    k_agg<512,512,2><<<NSENT, 256>>>(HSc, src_S, eS, oS,  aS, GSh);

    // per-head projection + bias + ELU (batched over heads via z); writes fp32 + fp16
    dim3 gp(CDIM/128, NSENT/128, 8);
    gemm_h<EPI_BIAS_ELU><<<gp, 256>>>(Gwh, Gwh, 320, WwTh, Uw, Uwh, bw, nullptr, nullptr,
        NSENT, CDIM, 320, 8*320, 320, HC, 320, (long)CDIM*320, 640, 640);
    gemm_h<EPI_BIAS_ELU><<<gp, 256>>>(Gsh, Gsh, 640, WsTh, Us, Ush, bs, nullptr, nullptr,
        NSENT, CDIM, 640, 8*640, 640, HC, 640, (long)CDIM*640, 640, 640);
    gemm_h<EPI_BIAS_ELU><<<gp, 256>>>(GSh, GSh, 512, WSTh, USec, USech, bS, nullptr, nullptr,
        NSENT, CDIM, 512, 8*512, 512, HC, 512, (long)CDIM*512, 640, 640);

    // fusion gates: implicit concat (A-split) + sigmoid-gate epilogue (fp32 E0/E1)
    dim3 gf(HC/128, NSENT/128, 1);
    gemm_h<EPI_FUSION><<<gf, 256>>>(Uwh, Ush, HC, Wf1Th, U1, U1h, bf1, Uw, Us,
        NSENT, HC, 2*HC, HC, 2*HC, HC, 0, 0, 0, 0);
    gemm_h<EPI_FUSION><<<gf, 256>>>(U1h, USech, HC, Wf2Th, U2, U2h, bf2, U1, USec,
        NSENT, HC, 2*HC, HC, 2*HC, HC, 0, 0, 0, 0);

    // FFN + residual
    dim3 g1(CDIM/128, NSENT/128, 1);
    gemm_h<EPI_BIAS_RELU><<<g1, 256>>>(U2h, U2h, HC, W1Th, Hh, Hhh, b1, nullptr, nullptr,
        NSENT, CDIM, HC, HC, HC, CDIM, 0, 0, 0, 0);
    gemm_h<EPI_RESID><<<g1, 256>>>(Hhh, Hhh, CDIM, W2Th, out, nullptr, b2, Hs, nullptr,
        NSENT, CDIM, CDIM, CDIM, CDIM, CDIM, 0, 0, 0, 0);
}

// round 16
// speedup vs baseline: 1.9356x; 1.9356x over previous
#include <cuda_runtime.h>
#include <cuda_fp16.h>
#include <math.h>
#include <stdint.h>

#define NSENT 4096
#define NWORD 65536
#define NSEC  512
#define NHEAD 8
#define CDIM  640
#define HC    5120
#define EW    65536
#define ES    32768
#define ESEC  4096
#define NEG_SLOPE 0.2f

// ---------------- scratch (__device__ globals, no allocation) ----------------
__device__ float g_Uw[NSENT*HC];
__device__ float g_Us[NSENT*HC];
__device__ float g_USec[NSENT*HC];
__device__ float g_U1[NSENT*HC];
__device__ float g_Hh[NSENT*CDIM];
__device__ float g_U2[NSENT*HC];
// fp16 operand copies (GEMM A inputs)
__device__ __half g_Uwh[NSENT*HC];
__device__ __half g_Ush[NSENT*HC];
__device__ __half g_USech[NSENT*HC];
__device__ __half g_U1h[NSENT*HC];
__device__ __half g_U2h[NSENT*HC];
__device__ __half g_Hhh[NSENT*CDIM];
__device__ __half g_Gwh[NSENT*NHEAD*320];
__device__ __half g_Gsh[NSENT*NHEAD*640];
__device__ __half g_GSh[NSENT*NHEAD*512];
// fp16 K-major transposed weights (GEMM B inputs, [N][K])
__device__ __half g_Wf1Th[(long)HC*2*HC];
__device__ __half g_Wf2Th[(long)HC*2*HC];
__device__ __half g_W1Th[CDIM*HC];
__device__ __half g_W2Th[CDIM*CDIM];
__device__ __half g_WwTh[NHEAD*CDIM*320];
__device__ __half g_WsTh[NHEAD*CDIM*640];
__device__ __half g_WSTh[NHEAD*CDIM*512];
// graph scratch
__device__ float g_Pws[300*8], g_Pwd[640*8], g_Pss[640*8], g_Psd[640*8], g_PSs[512*8], g_PSd[640*8];
__device__ float g_alws[NWORD*8];
__device__ float g_alwd[NSENT*8], g_alss[NSENT*8], g_alsd[NSENT*8], g_alSd[NSENT*8];
__device__ float g_alSs[NSEC*8];
__device__ float g_aw[EW*8], g_as[ES*8], g_aS[ESEC*8];
__device__ int   g_mw[NSENT*8], g_ms[NSENT*8], g_mS[NSENT*8];
__device__ float g_dw[NSENT*8], g_ds[NSENT*8], g_dS[NSENT*8];
__device__ int   g_cw[NSENT], g_cs[NSENT], g_cS[NSENT];
__device__ int   g_ow[NSENT+1], g_os[NSENT+1], g_oS[NSENT+1];
__device__ int   g_uw[NSENT], g_us[NSENT], g_uS[NSENT];
__device__ int   g_ew[EW], g_es[ES], g_eS[ESEC];

// ---------------- helpers ----------------
__device__ __forceinline__ int f2oi(float f){ int i=__float_as_int(f); return i>=0? i : (i ^ 0x7fffffff); }
__device__ __forceinline__ float oi2f(int i){ return __int_as_float(i>=0? i : (i ^ 0x7fffffff)); }

// ---------------- init ----------------
__global__ void k_init_all(int* m0, float* d0, int* c0,
                           int* m1, float* d1, int* c1,
                           int* m2, float* d2, int* c2){
    int i = blockIdx.x*blockDim.x + threadIdx.x;
    if (i < NSENT*8){
        m0[i] = (int)0x807FFFFF; d0[i] = 0.f;
        m1[i] = (int)0x807FFFFF; d1[i] = 0.f;
        m2[i] = (int)0x807FFFFF; d2[i] = 0.f;
    }
    if (i < NSENT){ c0[i] = 0; c1[i] = 0; c2[i] = 0; }
}

// ---------------- transpose + fp16 convert: BT[z][n][k] = (half)W[k][z*colstride + n] ----------------
__global__ void k_Tc(const float* __restrict__ W, __half* __restrict__ BT,
                     int Kin, int Kpad, int Nsub, int ldw, int colstride){
    __shared__ float t[32][33];
    int nb = blockIdx.x*32, kb = blockIdx.y*32;
    int x = threadIdx.x, y = threadIdx.y;
    long coff = (long)blockIdx.z*colstride;
    #pragma unroll
    for (int j = 0; j < 32; j += 8){
        int k = kb + y + j, n = nb + x;
        t[y+j][x] = (k < Kin && n < Nsub) ? W[(long)k*ldw + coff + n] : 0.f;
    }
    __syncthreads();
    __half* out = BT + (long)blockIdx.z*Nsub*Kpad;
    #pragma unroll
    for (int j = 0; j < 32; j += 8){
        int n = nb + y + j, k = kb + x;
        if (n < Nsub && k < Kpad) out[(long)n*Kpad + k] = __float2half_rn(t[x][y+j]);
    }
}

// ---------------- P[d,h] ----------------
__global__ void k_P(const float* __restrict__ W, const float* __restrict__ a,
                    float* __restrict__ P, int D){
    int gw   = (blockIdx.x*blockDim.x + threadIdx.x) >> 5;
    int lane = threadIdx.x & 31;
    if (gw >= D*8) return;
    int d = gw >> 3, h = gw & 7;
    const float* wr = W + (long)d*HC + h*CDIM;
    const float* ar = a + h*CDIM;
    float acc = 0.f;
    for (int c = lane; c < CDIM; c += 32) acc = fmaf(__ldg(&wr[c]), __ldg(&ar[c]), acc);
    #pragma unroll
    for (int o = 16; o; o >>= 1) acc += __shfl_xor_sync(0xffffffffu, acc, o);
    if (!lane) P[gw] = acc;
}

// ---------------- AL[n,h] ----------------
__global__ void k_xp(const float* __restrict__ X, const float* __restrict__ P,
                     float* __restrict__ AL, int N, int D){
    int row  = (blockIdx.x*blockDim.x + threadIdx.x) >> 5;
    int lane = threadIdx.x & 31;
    if (row >= N) return;
    const float* x = X + (long)row*D;
    float acc[8] = {0,0,0,0,0,0,0,0};
    for (int dd = lane; dd < D; dd += 32){
        float xv = __ldg(&x[dd]);
        const float* p = P + dd*8;
        #pragma unroll
        for (int h = 0; h < 8; h++) acc[h] = fmaf(xv, __ldg(&p[h]), acc[h]);
    }
    #pragma unroll
    for (int h = 0; h < 8; h++){
        #pragma unroll
        for (int o = 16; o; o >>= 1) acc[h] += __shfl_xor_sync(0xffffffffu, acc[h], o);
    }
    if (lane == 0){
        #pragma unroll
        for (int h = 0; h < 8; h++) AL[(long)row*8 + h] = acc[h];
    }
}

// ---------------- edge softmax ----------------
__global__ void k_logits(const int* __restrict__ src, const int* __restrict__ dst,
                         const float* __restrict__ als, const float* __restrict__ ald,
                         float* __restrict__ lg, int* __restrict__ segmax, int E){
    int e = blockIdx.x*blockDim.x + threadIdx.x;
    if (e >= E) return;
    int s = src[e], d = dst[e];
    #pragma unroll
    for (int h = 0; h < 8; h++){
        float v = __ldg(&als[s*8+h]) + __ldg(&ald[d*8+h]);
        v = v > 0.f ? v : NEG_SLOPE*v;
        lg[e*8+h] = v;
        atomicMax(&segmax[d*8+h], f2oi(v));
    }
}
__global__ void k_exp(const int* __restrict__ dst, float* __restrict__ lg,
                      const int* __restrict__ segmax, float* __restrict__ den, int E){
    int e = blockIdx.x*blockDim.x + threadIdx.x;
    if (e >= E) return;
    int d = dst[e];
    #pragma unroll
    for (int h = 0; h < 8; h++){
        float m  = oi2f(__ldg(&segmax[d*8+h]));
        float ex = expf(lg[e*8+h] - m);
        lg[e*8+h] = ex;
        atomicAdd(&den[d*8+h], ex);
    }
}
__global__ void k_alpha(const int* __restrict__ dst, float* __restrict__ lg,
                        const float* __restrict__ den, int E){
    int e = blockIdx.x*blockDim.x + threadIdx.x;
    if (e >= E) return;
    int d = dst[e];
    #pragma unroll
    for (int h = 0; h < 8; h++)
        lg[e*8+h] = lg[e*8+h] / (__ldg(&den[d*8+h]) + 1e-16f);
}

// ---------------- CSR build ----------------
__global__ void k_count(const int* __restrict__ dst, int* __restrict__ cnt, int E){
    int e = blockIdx.x*blockDim.x + threadIdx.x;
    if (e < E) atomicAdd(&cnt[dst[e]], 1);
}
__global__ void k_scan(const int* __restrict__ cnt, int* __restrict__ offs,
                       int* __restrict__ cur){
    __shared__ int sh[1024];
    int tid = threadIdx.x;
    int base = tid*4;
    int v0 = cnt[base], v1 = cnt[base+1], v2 = cnt[base+2], v3 = cnt[base+3];
    int sum = v0+v1+v2+v3;
    sh[tid] = sum; __syncthreads();
    for (int off = 1; off < 1024; off <<= 1){
        int t = (tid >= off) ? sh[tid-off] : 0;
        __syncthreads();
        sh[tid] += t;
        __syncthreads();
    }
    int run = sh[tid] - sum;
    offs[base] = run;   cur[base]   = run; run += v0;
    offs[base+1] = run; cur[base+1] = run; run += v1;
    offs[base+2] = run; cur[base+2] = run; run += v2;
    offs[base+3] = run; cur[base+3] = run; run += v3;
    if (tid == 1023) offs[NSENT] = run;
}
__global__ void k_scatter(const int* __restrict__ dst, int* __restrict__ cur,
                          int* __restrict__ eidx, int E){
    int e = blockIdx.x*blockDim.x + threadIdx.x;
    if (e < E) eidx[atomicAdd(&cur[dst[e]], 1)] = e;
}

// ---------------- per-dst aggregation -> fp16 (padded K) ----------------
template<int D, int DPAD, int COLS>
__global__ void k_agg(const float* __restrict__ X, const int* __restrict__ src,
                      const int* __restrict__ eidx, const int* __restrict__ offs,
                      const float* __restrict__ alpha, __half* __restrict__ G){
    int d = blockIdx.x, tid = threadIdx.x;
    float acc[COLS][8];
    #pragma unroll
    for (int ci = 0; ci < COLS; ci++)
        #pragma unroll
        for (int h = 0; h < 8; h++) acc[ci][h] = 0.f;
    int beg = offs[d], end = offs[d+1];
    for (int i = beg; i < end; i++){
        int e = eidx[i];
        int s = src[e];
        float a[8];
        #pragma unroll
        for (int h = 0; h < 8; h++) a[h] = __ldg(&alpha[e*8+h]);
        #pragma unroll
        for (int ci = 0; ci < COLS; ci++){
            int c = tid + ci*256;
            if (c < D){
                float x = __ldg(&X[(long)s*D + c]);
                #pragma unroll
                for (int h = 0; h < 8; h++) acc[ci][h] = fmaf(a[h], x, acc[ci][h]);
            }
        }
    }
    #pragma unroll
    for (int ci = 0; ci < COLS; ci++){
        int c = tid + ci*256;
        if (c < DPAD){
            #pragma unroll
            for (int h = 0; h < 8; h++){
                float v = (c < D) ? acc[ci][h] : 0.f;
                G[((long)d*8 + h)*DPAD + c] = __float2half_rn(v);
            }
        }
    }
}

// ---------------- FP16 tensor-core GEMM 128x128x32, line-friendly staging ----------------
// A [M][Ktot] half K-major (split A/A2 at ksplit, mult of 32); BT [N][Ktot] half K-major.
// As2[k2][m] stride 136 (frag-conflict-free); Bs2[n][k2] stride 20 (frag-conflict-free).
#define ASTR 136
#define BSTR 20
enum { EPI_BIAS_ELU = 0, EPI_BIAS_RELU, EPI_FUSION, EPI_RESID };

__device__ __forceinline__ void mma_f16(float* d, const uint32_t* a, const uint32_t* b){
    asm volatile(
        "mma.sync.aligned.m16n8k16.row.col.f32.f16.f16.f32 "
        "{%0,%1,%2,%3}, {%4,%5,%6,%7}, {%8,%9}, {%0,%1,%2,%3};"
        : "+f"(d[0]), "+f"(d[1]), "+f"(d[2]), "+f"(d[3])
        : "r"(a[0]), "r"(a[1]), "r"(a[2]), "r"(a[3]), "r"(b[0]), "r"(b[1]));
}

// straight-line staging macros (no lambdas)
#define GEMM_LDG(tt) do { \
    int k_ = (tt)*32 + spart*8; \
    const __half* pA0_ = (k_ < ksplit) ? (A  + (long)(bRow + srow)*lda + k_) \
                                       : (A2 + (long)(bRow + srow)*lda + (k_ - ksplit)); \
    pa[0] = *reinterpret_cast<const uint4*>(pA0_); \
    pb[0] = *reinterpret_cast<const uint4*>(BT + (long)(bCol + srow)*ldbt + k_); \
    const __half* pA1_ = (k_ < ksplit) ? (A  + (long)(bRow + srow + 64)*lda + k_) \
                                       : (A2 + (long)(bRow + srow + 64)*lda + (k_ - ksplit)); \
    pa[1] = *reinterpret_cast<const uint4*>(pA1_); \
    pb[1] = *reinterpret_cast<const uint4*>(BT + (long)(bCol + srow + 64)*ldbt + k_); \
} while(0)

#define GEMM_STS() do { \
    const uint32_t* sa0_ = reinterpret_cast<const uint32_t*>(&pa[0]); \
    const uint32_t* sb0_ = reinterpret_cast<const uint32_t*>(&pb[0]); \
    const uint32_t* sa1_ = reinterpret_cast<const uint32_t*>(&pa[1]); \
    const uint32_t* sb1_ = reinterpret_cast<const uint32_t*>(&pb[1]); \
    _Pragma("unroll") \
    for (int i_ = 0; i_ < 4; i_++){ \
        As2[(spart*4 + i_)*ASTR + srow]        = sa0_[i_]; \
        Bs2[srow*BSTR + spart*4 + i_]          = sb0_[i_]; \
        As2[(spart*4 + i_)*ASTR + srow + 64]   = sa1_[i_]; \
        Bs2[(srow + 64)*BSTR + spart*4 + i_]   = sb1_[i_]; \
    } \
} while(0)

template<int EPI>
__global__ __launch_bounds__(256,2)
void gemm_h(const __half* __restrict__ A, const __half* __restrict__ A2, int ksplit,
            const __half* __restrict__ BT, float* __restrict__ C, __half* __restrict__ Ch,
            const float* __restrict__ bias,
            const float* __restrict__ E0, const float* __restrict__ E1,
            int M, int N, int Ktot, int lda, int ldbt, int ldc,
            long sA, long sBT, long sC, int sBias){
    int z = blockIdx.z;
    A  += (long)z*sA;  A2 += (long)z*sA;  BT += (long)z*sBT;  C += (long)z*sC;
    if (Ch) Ch += (long)z*sC;
    const float* bp = bias + (long)z*sBias;

    __shared__ uint32_t As2[16*ASTR];
    __shared__ uint32_t Bs2[128*BSTR];
    int tid  = threadIdx.x;
    int wid  = tid >> 5, lane = tid & 31;
    int g    = lane >> 2, tig = lane & 3;
    int wm   = wid & 3, wn = wid >> 2;          // warp tile: 32(M) x 64(N)
    int m0   = wm*32, n0 = wn*64;
    int bRow = blockIdx.y*128, bCol = blockIdx.x*128;
    int srow = tid >> 2, spart = tid & 3;       // staging: 4 threads/row, 16B each

    float acc[2][8][4];
    #pragma unroll
    for (int mi = 0; mi < 2; mi++)
        #pragma unroll
        for (int j = 0; j < 8; j++)
            #pragma unroll
            for (int c = 0; c < 4; c++) acc[mi][j][c] = 0.f;

    uint4 pa[2], pb[2];
    int T = Ktot >> 5;
    GEMM_LDG(0);
    for (int t = 0; t < T; t++){
        GEMM_STS();
        __syncthreads();
        if (t + 1 < T) GEMM_LDG(t + 1);
        #pragma unroll
        for (int ks = 0; ks < 2; ks++){
            int kb = ks*8;
            uint32_t af[2][4];
            #pragma unroll
            for (int mi = 0; mi < 2; mi++){
                int mb = m0 + mi*16;
                af[mi][0] = As2[(kb+tig  )*ASTR + mb + g    ];
                af[mi][1] = As2[(kb+tig  )*ASTR + mb + g + 8];
                af[mi][2] = As2[(kb+tig+4)*ASTR + mb + g    ];
                af[mi][3] = As2[(kb+tig+4)*ASTR + mb + g + 8];
            }
            #pragma unroll
            for (int j = 0; j < 8; j++){
                int n = n0 + j*8 + g;
                uint32_t bf[2];
                bf[0] = Bs2[n*BSTR + kb + tig    ];
                bf[1] = Bs2[n*BSTR + kb + tig + 4];
                mma_f16(acc[0][j], af[0], bf);
                mma_f16(acc[1][j], af[1], bf);
            }
        }
        __syncthreads();
    }

    // epilogue: thread owns rows (m0+mi*16+g, +8), cols (n0+j*8+tig*2, +1)
    #pragma unroll
    for (int mi = 0; mi < 2; mi++){
        #pragma unroll
        for (int half = 0; half < 2; half++){
            int row = bRow + m0 + mi*16 + g + half*8;
            #pragma unroll
            for (int j = 0; j < 8; j++){
                int col = bCol + n0 + j*8 + tig*2;
                long idx = (long)row*ldc + col;
                float v0 = acc[mi][j][half*2+0] + bp[col];
                float v1 = acc[mi][j][half*2+1] + bp[col+1];
                float r0, r1;
                if (EPI == EPI_BIAS_ELU){
                    r0 = v0 > 0.f ? v0 : (expf(v0) - 1.f);
                    r1 = v1 > 0.f ? v1 : (expf(v1) - 1.f);
                } else if (EPI == EPI_BIAS_RELU){
                    r0 = fmaxf(v0, 0.f);
                    r1 = fmaxf(v1, 0.f);
                } else if (EPI == EPI_FUSION){
                    float z0 = 1.f/(1.f + expf(-v0));
                    float z1 = 1.f/(1.f + expf(-v1));
                    r0 = z0*E0[idx]   + (1.f - z0)*E1[idx];
                    r1 = z1*E0[idx+1] + (1.f - z1)*E1[idx+1];
                } else { // EPI_RESID
                    r0 = E0[idx]   + v0;
                    r1 = E0[idx+1] + v1;
                }
                *reinterpret_cast<float2*>(&C[idx]) = make_float2(r0, r1);
                if (Ch){
                    __half2 h2 = __floats2half2_rn(r0, r1);
                    *reinterpret_cast<__half2*>(&Ch[idx]) = h2;
                }
            }
        }
    }
}

// ---------------- host ----------------
#define SYMF(name, sym) float* name; cudaGetSymbolAddress((void**)&name, sym)
#define SYMH(name, sym) __half* name; cudaGetSymbolAddress((void**)&name, sym)
#define SYMI(name, sym) int*   name; cudaGetSymbolAddress((void**)&name, sym)

extern "C" void kernel_launch(void* const* d_in, const int* in_sizes, int n_in,
                              void* d_out, int out_size){
    const float* Hs    = (const float*)d_in[0];
    const float* Hw    = (const float*)d_in[1];
    const float* HSc   = (const float*)d_in[2];
    const int*   w2s   = (const int*)d_in[3];
    const int*   s2s   = (const int*)d_in[4];
    const int*   S2s   = (const int*)d_in[5];
    const float* Ww_src= (const float*)d_in[6];
    const float* Ww_dst= (const float*)d_in[7];
    const float* aw_src= (const float*)d_in[8];
    const float* aw_dst= (const float*)d_in[9];
    const float* bw    = (const float*)d_in[10];
    const float* Ws    = (const float*)d_in[11];
    const float* as_src= (const float*)d_in[12];
    const float* as_dst= (const float*)d_in[13];
    const float* bs    = (const float*)d_in[14];
    const float* WS_src= (const float*)d_in[15];
    const float* WS_dst= (const float*)d_in[16];
    const float* aS_src= (const float*)d_in[17];
    const float* aS_dst= (const float*)d_in[18];
    const float* bS    = (const float*)d_in[19];
    const float* Wf1   = (const float*)d_in[20];
    const float* bf1   = (const float*)d_in[21];
    const float* Wf2   = (const float*)d_in[22];
    const float* bf2   = (const float*)d_in[23];
    const float* W1    = (const float*)d_in[24];
    const float* b1    = (const float*)d_in[25];
    const float* W2    = (const float*)d_in[26];
    const float* b2    = (const float*)d_in[27];
    float* out = (float*)d_out;

    SYMF(Uw, g_Uw); SYMF(Us, g_Us); SYMF(USec, g_USec); SYMF(U1, g_U1); SYMF(U2, g_U2); SYMF(Hh, g_Hh);
    SYMH(Uwh, g_Uwh); SYMH(Ush, g_Ush); SYMH(USech, g_USech); SYMH(U1h, g_U1h); SYMH(U2h, g_U2h); SYMH(Hhh, g_Hhh);
    SYMH(Gwh, g_Gwh); SYMH(Gsh, g_Gsh); SYMH(GSh, g_GSh);
    SYMH(Wf1Th, g_Wf1Th); SYMH(Wf2Th, g_Wf2Th); SYMH(W1Th, g_W1Th); SYMH(W2Th, g_W2Th);
    SYMH(WwTh, g_WwTh); SYMH(WsTh, g_WsTh); SYMH(WSTh, g_WSTh);
    SYMF(Pws, g_Pws); SYMF(Pwd, g_Pwd); SYMF(Pss, g_Pss); SYMF(Psd, g_Psd);
    SYMF(PSs, g_PSs); SYMF(PSd, g_PSd);
    SYMF(alws, g_alws); SYMF(alwd, g_alwd); SYMF(alss, g_alss); SYMF(alsd, g_alsd);
    SYMF(alSs, g_alSs); SYMF(alSd, g_alSd);
    SYMF(aw, g_aw); SYMF(as, g_as); SYMF(aS, g_aS);
    SYMI(mw, g_mw); SYMI(ms, g_ms); SYMI(mS, g_mS);
    SYMF(dw, g_dw); SYMF(ds, g_ds); SYMF(dS, g_dS);
    SYMI(cw, g_cw); SYMI(cs, g_cs); SYMI(cS, g_cS);
    SYMI(ow, g_ow); SYMI(os_, g_os); SYMI(oS, g_oS);
    SYMI(uw, g_uw); SYMI(us, g_us); SYMI(uS, g_uS);
    SYMI(ew, g_ew); SYMI(es, g_es); SYMI(eS, g_eS);

    const int* src_w = w2s;            const int* dst_w = w2s + EW;
    const int* src_s = s2s;            const int* dst_s = s2s + ES;
    const int* src_S = S2s;            const int* dst_S = S2s + ESEC;

    // init
    k_init_all<<<(NSENT*8+255)/256, 256>>>(mw, dw, cw, ms, ds, cs, mS, dS, cS);

    // weight transpose + fp16 convert  (BT[z][n][k] layouts)
    dim3 tb(32, 8);
    k_Tc<<<dim3(20, 10, 8),   tb>>>(Ww_src, WwTh, 300,  320,  CDIM, HC,   CDIM);
    k_Tc<<<dim3(20, 20, 8),   tb>>>(Ws,     WsTh, 640,  640,  CDIM, HC,   CDIM);
    k_Tc<<<dim3(20, 16, 8),   tb>>>(WS_src, WSTh, 512,  512,  CDIM, HC,   CDIM);
    k_Tc<<<dim3(160, 320, 1), tb>>>(Wf1,    Wf1Th, 2*HC, 2*HC, HC,  HC,   0);
    k_Tc<<<dim3(160, 320, 1), tb>>>(Wf2,    Wf2Th, 2*HC, 2*HC, HC,  HC,   0);
    k_Tc<<<dim3(20, 160, 1),  tb>>>(W1,     W1Th,  HC,   HC,   CDIM, CDIM, 0);
    k_Tc<<<dim3(20, 20, 1),   tb>>>(W2,     W2Th,  CDIM, CDIM, CDIM, CDIM, 0);

    // per-head attention projection vectors
    k_P<<<300, 256>>>(Ww_src, aw_src, Pws, 300);
    k_P<<<640, 256>>>(Ww_dst, aw_dst, Pwd, 640);
    k_P<<<640, 256>>>(Ws,     as_src, Pss, 640);
    k_P<<<640, 256>>>(Ws,     as_dst, Psd, 640);
    k_P<<<512, 256>>>(WS_src, aS_src, PSs, 512);
    k_P<<<640, 256>>>(WS_dst, aS_dst, PSd, 640);

    // attention logits per node
    k_xp<<<NWORD/8, 256>>>(Hw,  Pws, alws, NWORD, 300);
    k_xp<<<NSENT/8, 256>>>(Hs,  Pwd, alwd, NSENT, 640);
    k_xp<<<NSENT/8, 256>>>(Hs,  Pss, alss, NSENT, 640);
    k_xp<<<NSENT/8, 256>>>(Hs,  Psd, alsd, NSENT, 640);
    k_xp<<<NSEC/8,  256>>>(HSc, PSs, alSs, NSEC,  512);
    k_xp<<<NSENT/8, 256>>>(Hs,  PSd, alSd, NSENT, 640);

    // CSR build
    k_count<<<EW/256, 256>>>(dst_w, cw, EW);
    k_count<<<ES/256, 256>>>(dst_s, cs, ES);
    k_count<<<ESEC/256, 256>>>(dst_S, cS, ESEC);
    k_scan<<<1, 1024>>>(cw, ow, uw);
    k_scan<<<1, 1024>>>(cs, os_, us);
    k_scan<<<1, 1024>>>(cS, oS, uS);
    k_scatter<<<EW/256, 256>>>(dst_w, uw, ew, EW);
    k_scatter<<<ES/256, 256>>>(dst_s, us, es, ES);
    k_scatter<<<ESEC/256, 256>>>(dst_S, uS, eS, ESEC);

    // edge softmax
    k_logits<<<EW/256, 256>>>(src_w, dst_w, alws, alwd, aw, mw, EW);
    k_logits<<<ES/256, 256>>>(src_s, dst_s, alss, alsd, as, ms, ES);
    k_logits<<<ESEC/256, 256>>>(src_S, dst_S, alSs, alSd, aS, mS, ESEC);
    k_exp<<<EW/256, 256>>>(dst_w, aw, mw, dw, EW);
    k_exp<<<ES/256, 256>>>(dst_s, as, ms, ds, ES);
    k_exp<<<ESEC/256, 256>>>(dst_S, aS, mS, dS, ESEC);
    k_alpha<<<EW/256, 256>>>(dst_w, aw, dw, EW);
    k_alpha<<<ES/256, 256>>>(dst_s, as, ds, ES);
    k_alpha<<<ESEC/256, 256>>>(dst_S, aS, dS, ESEC);

    // aggregate raw features per (dst, head) -> fp16 (K padded)
    k_agg<300,320,2><<<NSENT, 256>>>(Hw,  src_w, ew, ow,  aw, Gwh);
    k_agg<640,640,3><<<NSENT, 256>>>(Hs,  src_s, es, os_, as, Gsh);
    k_agg<512,512,2><<<NSENT, 256>>>(HSc, src_S, eS, oS,  aS, GSh);

    // per-head projection + bias + ELU (batched over heads via z); writes fp32 + fp16
    dim3 gp(CDIM/128, NSENT/128, 8);
    gemm_h<EPI_BIAS_ELU><<<gp, 256>>>(Gwh, Gwh, 320, WwTh, Uw, Uwh, bw, nullptr, nullptr,
        NSENT, CDIM, 320, 8*320, 320, HC, 320, (long)CDIM*320, 640, 640);
    gemm_h<EPI_BIAS_ELU><<<gp, 256>>>(Gsh, Gsh, 640, WsTh, Us, Ush, bs, nullptr, nullptr,
        NSENT, CDIM, 640, 8*640, 640, HC, 640, (long)CDIM*640, 640, 640);
    gemm_h<EPI_BIAS_ELU><<<gp, 256>>>(GSh, GSh, 512, WSTh, USec, USech, bS, nullptr, nullptr,
        NSENT, CDIM, 512, 8*512, 512, HC, 512, (long)CDIM*512, 640, 640);

    // fusion gates: implicit concat (A-split) + sigmoid-gate epilogue (fp32 E0/E1)
    dim3 gf(HC/128, NSENT/128, 1);
    gemm_h<EPI_FUSION><<<gf, 256>>>(Uwh, Ush, HC, Wf1Th, U1, U1h, bf1, Uw, Us,
        NSENT, HC, 2*HC, HC, 2*HC, HC, 0, 0, 0, 0);
    gemm_h<EPI_FUSION><<<gf, 256>>>(U1h, USech, HC, Wf2Th, U2, U2h, bf2, U1, USec,
        NSENT, HC, 2*HC, HC, 2*HC, HC, 0, 0, 0, 0);

    // FFN + residual
    dim3 g1(CDIM/128, NSENT/128, 1);
    gemm_h<EPI_BIAS_RELU><<<g1, 256>>>(U2h, U2h, HC, W1Th, Hh, Hhh, b1, nullptr, nullptr,
        NSENT, CDIM, HC, HC, HC, CDIM, 0, 0, 0, 0);
    gemm_h<EPI_RESID><<<g1, 256>>>(Hhh, Hhh, CDIM, W2Th, out, nullptr, b2, Hs, nullptr,
        NSENT, CDIM, CDIM, CDIM, CDIM, CDIM, 0, 0, 0, 0);
}